// round 2
// baseline (speedup 1.0000x reference)
#include <cuda_runtime.h>
#include <math.h>

#define NN    8192
#define TT    32
#define HH    64
#define EE    32768
#define EPAD  (EE + NN)          // edges + self loops
#define BBATCH 32
#define LHID  128
#define ROWS  (TT * NN)          // 262144

// ---------------- scratch (device globals; no runtime allocation) ------------
__device__ float g_x[ROWS * HH];   // proj out / attn2 out   [T][N][H]
__device__ float g_h[ROWS * HH];   // GEMM out (h)           [T][N][H]
__device__ float g_y[ROWS * HH];   // attn1 out              [T][N][H]
__device__ float g_as[ROWS * 4];   // a_src per head         [T][N][4]
__device__ float g_ad[ROWS * 4];   // a_dst per head         [T][N][4]
__device__ int   g_cnt[NN];
__device__ int   g_rowptr[NN + 1];
__device__ int   g_cur[NN];
__device__ int   g_srcs[EPAD];

__device__ __forceinline__ float sigmf(float x) { return 1.0f / (1.0f + expf(-x)); }

// ---------------- CSR build --------------------------------------------------
__global__ void k_cnt_init() {
    int i = blockIdx.x * blockDim.x + threadIdx.x;
    if (i < NN) g_cnt[i] = 1;    // self loop
}

__global__ void k_hist(const int* __restrict__ ei) {
    int i = blockIdx.x * blockDim.x + threadIdx.x;
    if (i < EE) atomicAdd(&g_cnt[ei[EE + i]], 1);
}

__global__ void k_scan() {       // 1 block, 1024 threads, NN = 8192 = 1024*8
    __shared__ int s[1024];
    int tid = threadIdx.x;
    int base = tid * 8;
    int v[8];
    int sum = 0;
#pragma unroll
    for (int j = 0; j < 8; j++) { v[j] = g_cnt[base + j]; sum += v[j]; }
    s[tid] = sum;
    __syncthreads();
    for (int off = 1; off < 1024; off <<= 1) {
        int add = (tid >= off) ? s[tid - off] : 0;
        __syncthreads();
        s[tid] += add;
        __syncthreads();
    }
    int run = (tid > 0) ? s[tid - 1] : 0;
#pragma unroll
    for (int j = 0; j < 8; j++) {
        g_rowptr[base + j] = run;
        g_cur[base + j]    = run;
        run += v[j];
    }
    if (tid == 1023) g_rowptr[NN] = run;
}

__global__ void k_scatter(const int* __restrict__ ei) {
    int i = blockIdx.x * blockDim.x + threadIdx.x;
    if (i < EE) {
        int src = ei[i];
        int dst = ei[EE + i];
        int p = atomicAdd(&g_cur[dst], 1);
        g_srcs[p] = src;
    } else if (i < EE + NN) {
        int n = i - EE;
        int p = atomicAdd(&g_cur[n], 1);
        g_srcs[p] = n;
    }
}

// ---------------- basin dual projection: x = relu([era5,bc]@Wc + bd@Wd + b) --
// 128 threads: 8 rows/block, 16 threads/row, each thread owns 4 outputs.
__global__ void k_proj(const float* __restrict__ era5, const float* __restrict__ bc,
                       const float* __restrict__ bd, const float* __restrict__ Wc,
                       const float* __restrict__ Wd, const float* __restrict__ b) {
    __shared__ float sWc[32 * 64];
    __shared__ float sWd[8 * 64];
    __shared__ float sb[64];
    for (int i = threadIdx.x; i < 32 * 64; i += 128) sWc[i] = Wc[i];
    for (int i = threadIdx.x; i < 8 * 64;  i += 128) sWd[i] = Wd[i];
    if (threadIdx.x < 64) sb[threadIdx.x] = b[threadIdx.x];
    __syncthreads();

    int o = (threadIdx.x & 15) * 4;
    int rl = threadIdx.x >> 4;
    int row = blockIdx.x * 8 + rl;            // row = t*NN + n
    int t = row / NN, n = row % NN;
    const float* e5  = era5 + ((size_t)n * TT + t) * 16;
    const float* bcn = bc + n * 16;
    const float* bdn = bd + n * 8;

    float a0 = sb[o], a1 = sb[o + 1], a2 = sb[o + 2], a3 = sb[o + 3];
#pragma unroll
    for (int k = 0; k < 16; k++) {
        float v = e5[k];
        const float* w = &sWc[k * 64 + o];
        a0 += v * w[0]; a1 += v * w[1]; a2 += v * w[2]; a3 += v * w[3];
    }
#pragma unroll
    for (int k = 0; k < 16; k++) {
        float v = bcn[k];
        const float* w = &sWc[(16 + k) * 64 + o];
        a0 += v * w[0]; a1 += v * w[1]; a2 += v * w[2]; a3 += v * w[3];
    }
#pragma unroll
    for (int k = 0; k < 8; k++) {
        float v = bdn[k];
        const float* w = &sWd[k * 64 + o];
        a0 += v * w[0]; a1 += v * w[1]; a2 += v * w[2]; a3 += v * w[3];
    }
    float4 r;
    r.x = fmaxf(a0, 0.f); r.y = fmaxf(a1, 0.f); r.z = fmaxf(a2, 0.f); r.w = fmaxf(a3, 0.f);
    *(float4*)&g_x[(size_t)row * 64 + o] = r;
}

// ---------------- GAT GEMM: h = x@W ; fused a_s/a_d --------------------------
__global__ void k_gemm(const float* __restrict__ xin, const float* __restrict__ W,
                       const float* __restrict__ asrc, const float* __restrict__ adst,
                       float* __restrict__ hout, float* __restrict__ as_,
                       float* __restrict__ ad_) {
    __shared__ float sW[64 * 64];
    __shared__ float sx[8][64];
    __shared__ float sas[64], sad[64];
    for (int i = threadIdx.x; i < 64 * 64; i += 128) sW[i] = W[i];
    if (threadIdx.x < 64) { sas[threadIdx.x] = asrc[threadIdx.x]; sad[threadIdx.x] = adst[threadIdx.x]; }
    int base = blockIdx.x * 8;
    for (int i = threadIdx.x; i < 512; i += 128)
        sx[i >> 6][i & 63] = xin[(size_t)base * 64 + i];
    __syncthreads();

    int o = (threadIdx.x & 15) * 4;
    int rl = threadIdx.x >> 4;
    const float* xr = sx[rl];
    float a0 = 0, a1 = 0, a2 = 0, a3 = 0;
#pragma unroll
    for (int k = 0; k < 64; k++) {
        float xk = xr[k];
        float4 w = *(const float4*)&sW[k * 64 + o];
        a0 += xk * w.x; a1 += xk * w.y; a2 += xk * w.z; a3 += xk * w.w;
    }
    size_t row = base + rl;
    float4 r; r.x = a0; r.y = a1; r.z = a2; r.w = a3;
    *(float4*)&hout[row * 64 + o] = r;

    float ps = a0 * sas[o] + a1 * sas[o + 1] + a2 * sas[o + 2] + a3 * sas[o + 3];
    float pd = a0 * sad[o] + a1 * sad[o + 1] + a2 * sad[o + 2] + a3 * sad[o + 3];
    ps += __shfl_xor_sync(0xffffffffu, ps, 1); ps += __shfl_xor_sync(0xffffffffu, ps, 2);
    pd += __shfl_xor_sync(0xffffffffu, pd, 1); pd += __shfl_xor_sync(0xffffffffu, pd, 2);
    int og = threadIdx.x & 15;
    if ((og & 3) == 0) {
        int head = og >> 2;
        as_[row * 4 + head] = ps;
        ad_[row * 4 + head] = pd;
    }
}

// ---------------- GAT attention: one warp per (t, dst), online softmax -------
__global__ void k_attn(const float* __restrict__ h, const float* __restrict__ as_,
                       const float* __restrict__ ad_, const float* __restrict__ bias,
                       float* __restrict__ out, int dorelu) {
    int wid  = blockIdx.x * 4 + (threadIdx.x >> 5);
    int lane = threadIdx.x & 31;
    int t = wid / NN;
    int dst = wid - t * NN;
    size_t tbase = (size_t)t * NN;

    float adh = 0.f;
    if (lane < 4) adh = ad_[(tbase + dst) * 4 + lane];
    int s0 = g_rowptr[dst], s1 = g_rowptr[dst + 1];

    int hd0 = lane >> 4;        // head of dim (lane)
    int hd1 = 2 + (lane >> 4);  // head of dim (lane+32)

    float m = -INFINITY, den = 0.f, acc0 = 0.f, acc1 = 0.f;
    for (int j = s0; j < s1; j++) {
        int src = g_srcs[j];
        float e = 0.f;
        if (lane < 4) {
            float asv = as_[(tbase + src) * 4 + lane];
            e = asv + adh;
            e = (e > 0.f) ? e : 0.2f * e;     // leaky_relu 0.2
        }
        float nm = fmaxf(m, e);
        float sc = __expf(m - nm);
        float w  = __expf(e - nm);
        den = den * sc + w;
        m = nm;
        float sc0 = __shfl_sync(0xffffffffu, sc, hd0);
        float w0  = __shfl_sync(0xffffffffu, w,  hd0);
        float sc1 = __shfl_sync(0xffffffffu, sc, hd1);
        float w1  = __shfl_sync(0xffffffffu, w,  hd1);
        const float* hr = &h[(tbase + src) * 64];
        float hv0 = hr[lane], hv1 = hr[lane + 32];
        acc0 = acc0 * sc0 + w0 * hv0;
        acc1 = acc1 * sc1 + w1 * hv1;
    }
    float d0 = __shfl_sync(0xffffffffu, den, hd0) + 1e-16f;
    float d1 = __shfl_sync(0xffffffffu, den, hd1) + 1e-16f;
    float o0 = acc0 / d0 + bias[lane];
    float o1 = acc1 / d1 + bias[lane + 32];
    if (dorelu) { o0 = fmaxf(o0, 0.f); o1 = fmaxf(o1, 0.f); }
    out[(tbase + dst) * 64 + lane]      = o0;
    out[(tbase + dst) * 64 + lane + 32] = o1;
}

// ---------------- river proj + LSTM + CMAL head: 1 block per gauge -----------
__global__ void k_lstm(const float* __restrict__ rc, const float* __restrict__ rd,
                       const float* __restrict__ Wc_r, const float* __restrict__ Wd_r,
                       const float* __restrict__ b_r,
                       const float* __restrict__ Wi, const float* __restrict__ Wh,
                       const float* __restrict__ lb,
                       const float* __restrict__ hW, const float* __restrict__ hb,
                       const int* __restrict__ nodes, float* __restrict__ outp) {
    __shared__ float sWc[80 * 64];     // 20KB
    __shared__ float sWd[8 * 64];
    __shared__ float sbr[64];
    __shared__ float shW[128 * 12];    // 6KB
    __shared__ float shb[12];
    __shared__ float sh[128], scc[128], sx[64], sgate[512], zsh[12];
    __shared__ int snode;

    int b = blockIdx.x, tid = threadIdx.x;
    for (int i = tid; i < 80 * 64; i += 512) sWc[i] = Wc_r[i];
    for (int i = tid; i < 8 * 64;  i += 512) sWd[i] = Wd_r[i];
    for (int i = tid; i < 128 * 12; i += 512) shW[i] = hW[i];
    if (tid < 64)  sbr[tid] = b_r[tid];
    if (tid < 12)  shb[tid] = hb[tid];
    if (tid < 128) { sh[tid] = 0.f; scc[tid] = 0.f; }
    if (tid == 0) {
        int s = 0;
        for (int i = 0; i < b; i++) s += nodes[i];
        snode = s;
    }
    __syncthreads();

    int node0 = snode;
    const float* rcb = rc + b * 16;
    const float* rdb = rd + b * 8;

    for (int t = 0; t < TT; t++) {
        // series[b][t] = relu([sampled, rc] @ Wc_r + rd @ Wd_r + b_r)
        if (tid < 64) {
            float a = sbr[tid];
            const float* sm = &g_x[((size_t)t * NN + node0) * 64];
#pragma unroll 8
            for (int k = 0; k < 64; k++) a += sm[k] * sWc[k * 64 + tid];
#pragma unroll
            for (int k = 0; k < 16; k++) a += rcb[k] * sWc[(64 + k) * 64 + tid];
#pragma unroll
            for (int k = 0; k < 8;  k++) a += rdb[k] * sWd[k * 64 + tid];
            sx[tid] = fmaxf(a, 0.f);
        }
        __syncthreads();
        // gates: one thread per gate column
        {
            float g = lb[tid];
#pragma unroll 8
            for (int k = 0; k < 64;  k++) g += sx[k] * Wi[k * 512 + tid];
#pragma unroll 8
            for (int k = 0; k < 128; k++) g += sh[k] * Wh[k * 512 + tid];
            sgate[tid] = g;
        }
        __syncthreads();
        if (tid < 128) {
            float ig = sgate[tid], fg = sgate[128 + tid];
            float gg = sgate[256 + tid], og = sgate[384 + tid];
            float c = sigmf(fg) * scc[tid] + sigmf(ig) * tanhf(gg);
            float hv = sigmf(og) * tanhf(c);
            scc[tid] = c;
            sh[tid] = hv;
        }
        __syncthreads();
        if (tid < 12) {
            float z = shb[tid];
#pragma unroll 8
            for (int k = 0; k < 128; k++) z += sh[k] * shW[k * 12 + tid];
            zsh[tid] = z;
        }
        __syncthreads();
        if (tid < 12) {
            float z = zsh[tid];
            float outv;
            int g = tid / 3;
            if (g == 0) outv = z;
            else if (g == 1) outv = ((z > 20.f) ? z : log1pf(expf(z))) + 1e-3f;
            else if (g == 2) outv = sigmf(z);
            else {
                float z0 = zsh[9], z1 = zsh[10], z2 = zsh[11];
                float mm = fmaxf(z0, fmaxf(z1, z2));
                float s = expf(z0 - mm) + expf(z1 - mm) + expf(z2 - mm);
                outv = expf(z - mm) / s;
            }
            outp[((size_t)b * TT + t) * 12 + tid] = outv;
        }
        __syncthreads();
    }
    if (tid < 128) {
        outp[BBATCH * TT * 12 + b * 128 + tid]               = sh[tid];
        outp[BBATCH * TT * 12 + BBATCH * 128 + b * 128 + tid] = scc[tid];
    }
}

// ---------------- launch -----------------------------------------------------
extern "C" void kernel_launch(void* const* d_in, const int* in_sizes, int n_in,
                              void* d_out, int out_size) {
    const float* era5  = (const float*)d_in[0];
    const float* bc    = (const float*)d_in[1];
    const float* bd    = (const float*)d_in[2];
    const float* rc    = (const float*)d_in[3];
    const float* rd    = (const float*)d_in[4];
    const float* Wc_b  = (const float*)d_in[5];
    const float* Wd_b  = (const float*)d_in[6];
    const float* b_b   = (const float*)d_in[7];
    const float* W1    = (const float*)d_in[8];
    const float* asrc1 = (const float*)d_in[9];
    const float* adst1 = (const float*)d_in[10];
    const float* b1    = (const float*)d_in[11];
    const float* W2    = (const float*)d_in[12];
    const float* asrc2 = (const float*)d_in[13];
    const float* adst2 = (const float*)d_in[14];
    const float* b2    = (const float*)d_in[15];
    const float* Wc_r  = (const float*)d_in[16];
    const float* Wd_r  = (const float*)d_in[17];
    const float* b_r   = (const float*)d_in[18];
    const float* Wi    = (const float*)d_in[19];
    const float* Wh    = (const float*)d_in[20];
    const float* lb    = (const float*)d_in[21];
    const float* hW    = (const float*)d_in[22];
    const float* hb    = (const float*)d_in[23];
    const int*   ei    = (const int*)d_in[24];
    const int*   nodes = (const int*)d_in[25];
    float* outp = (float*)d_out;

    float *p_x, *p_h, *p_y, *p_as, *p_ad;
    cudaGetSymbolAddress((void**)&p_x,  g_x);
    cudaGetSymbolAddress((void**)&p_h,  g_h);
    cudaGetSymbolAddress((void**)&p_y,  g_y);
    cudaGetSymbolAddress((void**)&p_as, g_as);
    cudaGetSymbolAddress((void**)&p_ad, g_ad);

    // CSR build
    k_cnt_init<<<NN / 256, 256>>>();
    k_hist<<<EE / 256, 256>>>(ei);
    k_scan<<<1, 1024>>>();
    k_scatter<<<(EPAD + 255) / 256, 256>>>(ei);

    // basin projection
    k_proj<<<ROWS / 8, 128>>>(era5, bc, bd, Wc_b, Wd_b, b_b);

    // GAT layer 1
    k_gemm<<<ROWS / 8, 128>>>(p_x, W1, asrc1, adst1, p_h, p_as, p_ad);
    k_attn<<<ROWS / 4, 128>>>(p_h, p_as, p_ad, b1, p_y, 1);

    // GAT layer 2
    k_gemm<<<ROWS / 8, 128>>>(p_y, W2, asrc2, adst2, p_h, p_as, p_ad);
    k_attn<<<ROWS / 4, 128>>>(p_h, p_as, p_ad, b2, p_x, 0);

    // river proj + LSTM + head
    k_lstm<<<BBATCH, 512>>>(rc, rd, Wc_r, Wd_r, b_r, Wi, Wh, lb, hW, hb, nodes, outp);
}

// round 3
// speedup vs baseline: 1.1758x; 1.1758x over previous
#include <cuda_runtime.h>
#include <math.h>

#define NN    8192
#define TT    32
#define HH    64
#define EE    32768
#define EPAD  (EE + NN)
#define BBATCH 32
#define LHID  128
#define ROWS  (TT * NN)          // 262144

typedef unsigned long long ull;

// ---------------- scratch ----------------------------------------------------
__device__ float g_x[ROWS * HH];
__device__ float g_h[ROWS * HH];
__device__ float g_y[ROWS * HH];
__device__ float g_as[ROWS * 4];
__device__ float g_ad[ROWS * 4];
__device__ int   g_cnt[NN];
__device__ int   g_rowptr[NN + 1];
__device__ int   g_cur[NN];
__device__ int   g_srcs[EPAD];

__device__ __forceinline__ float sigmf(float x) { return 1.0f / (1.0f + expf(-x)); }

__device__ __forceinline__ ull fma2(ull a, ull b, ull c) {
    ull d;
    asm("fma.rn.f32x2 %0, %1, %2, %3;" : "=l"(d) : "l"(a), "l"(b), "l"(c));
    return d;
}
__device__ __forceinline__ ull pack2(float x) {
    ull d;
    asm("mov.b64 %0, {%1, %1};" : "=l"(d) : "f"(x));
    return d;
}
__device__ __forceinline__ void unpack2(ull v, float& lo, float& hi) {
    asm("mov.b64 {%0, %1}, %2;" : "=f"(lo), "=f"(hi) : "l"(v));
}

// ---------------- CSR build --------------------------------------------------
__global__ void k_cnt_init() {
    int i = blockIdx.x * blockDim.x + threadIdx.x;
    if (i < NN) g_cnt[i] = 1;
}
__global__ void k_hist(const int* __restrict__ ei) {
    int i = blockIdx.x * blockDim.x + threadIdx.x;
    if (i < EE) atomicAdd(&g_cnt[ei[EE + i]], 1);
}
__global__ void k_scan() {
    __shared__ int s[1024];
    int tid = threadIdx.x;
    int base = tid * 8;
    int v[8];
    int sum = 0;
#pragma unroll
    for (int j = 0; j < 8; j++) { v[j] = g_cnt[base + j]; sum += v[j]; }
    s[tid] = sum;
    __syncthreads();
    for (int off = 1; off < 1024; off <<= 1) {
        int add = (tid >= off) ? s[tid - off] : 0;
        __syncthreads();
        s[tid] += add;
        __syncthreads();
    }
    int run = (tid > 0) ? s[tid - 1] : 0;
#pragma unroll
    for (int j = 0; j < 8; j++) {
        g_rowptr[base + j] = run;
        g_cur[base + j]    = run;
        run += v[j];
    }
    if (tid == 1023) g_rowptr[NN] = run;
}
__global__ void k_scatter(const int* __restrict__ ei) {
    int i = blockIdx.x * blockDim.x + threadIdx.x;
    if (i < EE) {
        int p = atomicAdd(&g_cur[ei[EE + i]], 1);
        g_srcs[p] = ei[i];
    } else if (i < EE + NN) {
        int n = i - EE;
        int p = atomicAdd(&g_cur[n], 1);
        g_srcs[p] = n;
    }
}

// ---------------- basin projection: 32 rows/block, 512 threads ---------------
__global__ void k_proj(const float* __restrict__ era5, const float* __restrict__ bc,
                       const float* __restrict__ bd, const float* __restrict__ Wc,
                       const float* __restrict__ Wd, const float* __restrict__ b) {
    __shared__ float sWc[32 * 64];
    __shared__ float sWd[8 * 64];
    __shared__ float sb[64];
    for (int i = threadIdx.x; i < 32 * 64; i += 512) sWc[i] = Wc[i];
    for (int i = threadIdx.x; i < 8 * 64;  i += 512) sWd[i] = Wd[i];
    if (threadIdx.x < 64) sb[threadIdx.x] = b[threadIdx.x];
    __syncthreads();

    int o = (threadIdx.x & 15) * 4;
    int rl = threadIdx.x >> 4;
    int row = blockIdx.x * 32 + rl;
    int t = row / NN, n = row % NN;
    const float* e5  = era5 + ((size_t)n * TT + t) * 16;
    const float* bcn = bc + n * 16;
    const float* bdn = bd + n * 8;

    float a0 = sb[o], a1 = sb[o + 1], a2 = sb[o + 2], a3 = sb[o + 3];
#pragma unroll
    for (int k = 0; k < 16; k++) {
        float v = e5[k];
        const float* w = &sWc[k * 64 + o];
        a0 += v * w[0]; a1 += v * w[1]; a2 += v * w[2]; a3 += v * w[3];
    }
#pragma unroll
    for (int k = 0; k < 16; k++) {
        float v = bcn[k];
        const float* w = &sWc[(16 + k) * 64 + o];
        a0 += v * w[0]; a1 += v * w[1]; a2 += v * w[2]; a3 += v * w[3];
    }
#pragma unroll
    for (int k = 0; k < 8; k++) {
        float v = bdn[k];
        const float* w = &sWd[k * 64 + o];
        a0 += v * w[0]; a1 += v * w[1]; a2 += v * w[2]; a3 += v * w[3];
    }
    float4 r;
    r.x = fmaxf(a0, 0.f); r.y = fmaxf(a1, 0.f); r.z = fmaxf(a2, 0.f); r.w = fmaxf(a3, 0.f);
    *(float4*)&g_x[(size_t)row * 64 + o] = r;
}

// ---------------- GAT GEMM: 64x64 tile, f32x2 FMA, fused a_s/a_d -------------
// 128 threads: cg = tid&7 owns 8 cols, rg = tid>>3 owns 4 rows.
__global__ void __launch_bounds__(128) k_gemm(
        const float* __restrict__ xin, const float* __restrict__ W,
        const float* __restrict__ asrc, const float* __restrict__ adst,
        float* __restrict__ hout, float* __restrict__ as_, float* __restrict__ ad_) {
    __shared__ float sW[64 * 64];      // [k][n]
    __shared__ float sX[64][65];       // [r][k] padded
    __shared__ float sas[64], sad[64];
    int tid = threadIdx.x;
    for (int i = tid; i < 1024; i += 128)
        ((float4*)sW)[i] = ((const float4*)W)[i];
    if (tid < 64) { sas[tid] = asrc[tid]; sad[tid] = adst[tid]; }
    size_t base = (size_t)blockIdx.x * 64;
    {
        const float4* xg = (const float4*)(xin + base * 64);
        for (int i = tid; i < 1024; i += 128) {
            float4 v = xg[i];
            int r = i >> 4, k4 = (i & 15) * 4;
            sX[r][k4] = v.x; sX[r][k4 + 1] = v.y; sX[r][k4 + 2] = v.z; sX[r][k4 + 3] = v.w;
        }
    }
    __syncthreads();

    int cg = tid & 7, rg = tid >> 3;
    int o = cg * 8, r0 = rg * 4;
    const ull* sW64 = (const ull*)sW;

    ull a00 = 0, a01 = 0, a02 = 0, a03 = 0;
    ull a10 = 0, a11 = 0, a12 = 0, a13 = 0;
    ull a20 = 0, a21 = 0, a22 = 0, a23 = 0;
    ull a30 = 0, a31 = 0, a32 = 0, a33 = 0;

#pragma unroll 8
    for (int k = 0; k < 64; k++) {
        ull xp0 = pack2(sX[r0][k]);
        ull xp1 = pack2(sX[r0 + 1][k]);
        ull xp2 = pack2(sX[r0 + 2][k]);
        ull xp3 = pack2(sX[r0 + 3][k]);
        const ull* wr = sW64 + k * 32 + cg * 4;
        ull w0 = wr[0], w1 = wr[1], w2 = wr[2], w3 = wr[3];
        a00 = fma2(xp0, w0, a00); a01 = fma2(xp0, w1, a01);
        a02 = fma2(xp0, w2, a02); a03 = fma2(xp0, w3, a03);
        a10 = fma2(xp1, w0, a10); a11 = fma2(xp1, w1, a11);
        a12 = fma2(xp1, w2, a12); a13 = fma2(xp1, w3, a13);
        a20 = fma2(xp2, w0, a20); a21 = fma2(xp2, w1, a21);
        a22 = fma2(xp2, w2, a22); a23 = fma2(xp2, w3, a23);
        a30 = fma2(xp3, w0, a30); a31 = fma2(xp3, w1, a31);
        a32 = fma2(xp3, w2, a32); a33 = fma2(xp3, w3, a33);
    }

    int head = cg >> 1;
#pragma unroll
    for (int i = 0; i < 4; i++) {
        ull p0, p1, p2, p3;
        if (i == 0) { p0 = a00; p1 = a01; p2 = a02; p3 = a03; }
        else if (i == 1) { p0 = a10; p1 = a11; p2 = a12; p3 = a13; }
        else if (i == 2) { p0 = a20; p1 = a21; p2 = a22; p3 = a23; }
        else { p0 = a30; p1 = a31; p2 = a32; p3 = a33; }
        float v0, v1, v2, v3, v4, v5, v6, v7;
        unpack2(p0, v0, v1); unpack2(p1, v2, v3);
        unpack2(p2, v4, v5); unpack2(p3, v6, v7);
        size_t row = base + r0 + i;
        float4 lo; lo.x = v0; lo.y = v1; lo.z = v2; lo.w = v3;
        float4 hi; hi.x = v4; hi.y = v5; hi.z = v6; hi.w = v7;
        *(float4*)&hout[row * 64 + o] = lo;
        *(float4*)&hout[row * 64 + o + 4] = hi;
        float ps = v0 * sas[o] + v1 * sas[o + 1] + v2 * sas[o + 2] + v3 * sas[o + 3]
                 + v4 * sas[o + 4] + v5 * sas[o + 5] + v6 * sas[o + 6] + v7 * sas[o + 7];
        float pd = v0 * sad[o] + v1 * sad[o + 1] + v2 * sad[o + 2] + v3 * sad[o + 3]
                 + v4 * sad[o + 4] + v5 * sad[o + 5] + v6 * sad[o + 6] + v7 * sad[o + 7];
        ps += __shfl_xor_sync(0xffffffffu, ps, 1);
        pd += __shfl_xor_sync(0xffffffffu, pd, 1);
        if ((cg & 1) == 0) {
            as_[row * 4 + head] = ps;
            ad_[row * 4 + head] = pd;
        }
    }
}

// ---------------- GAT attention: warp per (t,dst), edge-parallel softmax -----
__global__ void __launch_bounds__(128) k_attn(
        const float* __restrict__ h, const float* __restrict__ as_,
        const float* __restrict__ ad_, const float* __restrict__ bias,
        float* __restrict__ out, int dorelu) {
    __shared__ float s_w[4][32][4];
    __shared__ int   s_src[4][32];
    int wp   = threadIdx.x >> 5;
    int lane = threadIdx.x & 31;
    int wid  = blockIdx.x * 4 + wp;
    int t = wid >> 13;                 // / NN (8192)
    int dst = wid & (NN - 1);
    size_t tbase = (size_t)t * NN;

    float4 adh = *(const float4*)&ad_[(tbase + dst) * 4];
    int s0 = g_rowptr[dst], s1 = g_rowptr[dst + 1];

    float m0 = -INFINITY, m1 = -INFINITY, m2 = -INFINITY, m3 = -INFINITY;
    float den0 = 0.f, den1 = 0.f, den2 = 0.f, den3 = 0.f;
    float acc0 = 0.f, acc1 = 0.f;

    for (int c0 = s0; c0 < s1; c0 += 32) {
        int j = c0 + lane;
        bool valid = j < s1;
        int src = valid ? g_srcs[j] : 0;
        float e0 = -INFINITY, e1 = -INFINITY, e2 = -INFINITY, e3 = -INFINITY;
        if (valid) {
            float4 a = *(const float4*)&as_[(tbase + src) * 4];
            e0 = a.x + adh.x; e0 = (e0 > 0.f) ? e0 : 0.2f * e0;
            e1 = a.y + adh.y; e1 = (e1 > 0.f) ? e1 : 0.2f * e1;
            e2 = a.z + adh.z; e2 = (e2 > 0.f) ? e2 : 0.2f * e2;
            e3 = a.w + adh.w; e3 = (e3 > 0.f) ? e3 : 0.2f * e3;
        }
        float c0m = e0, c1m = e1, c2m = e2, c3m = e3;
#pragma unroll
        for (int off = 16; off; off >>= 1) {
            c0m = fmaxf(c0m, __shfl_xor_sync(0xffffffffu, c0m, off));
            c1m = fmaxf(c1m, __shfl_xor_sync(0xffffffffu, c1m, off));
            c2m = fmaxf(c2m, __shfl_xor_sync(0xffffffffu, c2m, off));
            c3m = fmaxf(c3m, __shfl_xor_sync(0xffffffffu, c3m, off));
        }
        float n0 = fmaxf(m0, c0m), n1 = fmaxf(m1, c1m);
        float n2 = fmaxf(m2, c2m), n3 = fmaxf(m3, c3m);
        float r0 = __expf(m0 - n0), r1 = __expf(m1 - n1);
        float r2 = __expf(m2 - n2), r3 = __expf(m3 - n3);
        den0 *= r0; den1 *= r1; den2 *= r2; den3 *= r3;
        acc0 *= (lane < 16) ? r0 : r1;
        acc1 *= (lane < 16) ? r2 : r3;
        float w0 = __expf(e0 - n0), w1 = __expf(e1 - n1);
        float w2 = __expf(e2 - n2), w3 = __expf(e3 - n3);
        s_w[wp][lane][0] = w0; s_w[wp][lane][1] = w1;
        s_w[wp][lane][2] = w2; s_w[wp][lane][3] = w3;
        s_src[wp][lane] = src;
        float d0 = w0, d1 = w1, d2 = w2, d3 = w3;
#pragma unroll
        for (int off = 16; off; off >>= 1) {
            d0 += __shfl_xor_sync(0xffffffffu, d0, off);
            d1 += __shfl_xor_sync(0xffffffffu, d1, off);
            d2 += __shfl_xor_sync(0xffffffffu, d2, off);
            d3 += __shfl_xor_sync(0xffffffffu, d3, off);
        }
        den0 += d0; den1 += d1; den2 += d2; den3 += d3;
        m0 = n0; m1 = n1; m2 = n2; m3 = n3;
        __syncwarp();
        int cn = s1 - c0; if (cn > 32) cn = 32;
        int h0 = lane >> 4;        // 0/1
        for (int j2 = 0; j2 < cn; j2++) {
            float wa = s_w[wp][j2][h0];
            float wb = s_w[wp][j2][2 + h0];
            int sj = s_src[wp][j2];
            const float* hr = &h[(tbase + sj) * 64];
            acc0 += wa * hr[lane];
            acc1 += wb * hr[lane + 32];
        }
        __syncwarp();
    }
    float da = ((lane < 16) ? den0 : den1) + 1e-16f;
    float db = ((lane < 16) ? den2 : den3) + 1e-16f;
    float o0 = acc0 / da + bias[lane];
    float o1 = acc1 / db + bias[lane + 32];
    if (dorelu) { o0 = fmaxf(o0, 0.f); o1 = fmaxf(o1, 0.f); }
    out[(tbase + dst) * 64 + lane]      = o0;
    out[(tbase + dst) * 64 + lane + 32] = o1;
}

// ---------------- river proj + LSTM + CMAL head ------------------------------
__global__ void k_lstm(const float* __restrict__ rc, const float* __restrict__ rd,
                       const float* __restrict__ Wc_r, const float* __restrict__ Wd_r,
                       const float* __restrict__ b_r,
                       const float* __restrict__ Wi, const float* __restrict__ Wh,
                       const float* __restrict__ lb,
                       const float* __restrict__ hW, const float* __restrict__ hb,
                       const int* __restrict__ nodes, float* __restrict__ outp) {
    __shared__ float sWc[80 * 64];
    __shared__ float sWd[8 * 64];
    __shared__ float sbr[64];
    __shared__ float shW[128 * 12];
    __shared__ float shb[12];
    __shared__ float sh[128], scc[128], sx[64], sgate[512], zsh[12];
    __shared__ int snode;

    int b = blockIdx.x, tid = threadIdx.x;
    for (int i = tid; i < 80 * 64; i += 512) sWc[i] = Wc_r[i];
    for (int i = tid; i < 8 * 64;  i += 512) sWd[i] = Wd_r[i];
    for (int i = tid; i < 128 * 12; i += 512) shW[i] = hW[i];
    if (tid < 64)  sbr[tid] = b_r[tid];
    if (tid < 12)  shb[tid] = hb[tid];
    if (tid < 128) { sh[tid] = 0.f; scc[tid] = 0.f; }
    if (tid == 0) {
        int s = 0;
        for (int i = 0; i < b; i++) s += nodes[i];
        snode = s;
    }
    __syncthreads();

    int node0 = snode;
    const float* rcb = rc + b * 16;
    const float* rdb = rd + b * 8;

    for (int t = 0; t < TT; t++) {
        if (tid < 64) {
            float a0 = sbr[tid], a1 = 0.f, a2 = 0.f, a3 = 0.f;
            const float* sm = &g_x[((size_t)t * NN + node0) * 64];
#pragma unroll
            for (int k = 0; k < 64; k += 4) {
                a0 += sm[k] * sWc[k * 64 + tid];
                a1 += sm[k + 1] * sWc[(k + 1) * 64 + tid];
                a2 += sm[k + 2] * sWc[(k + 2) * 64 + tid];
                a3 += sm[k + 3] * sWc[(k + 3) * 64 + tid];
            }
#pragma unroll
            for (int k = 0; k < 16; k += 4) {
                a0 += rcb[k] * sWc[(64 + k) * 64 + tid];
                a1 += rcb[k + 1] * sWc[(64 + k + 1) * 64 + tid];
                a2 += rcb[k + 2] * sWc[(64 + k + 2) * 64 + tid];
                a3 += rcb[k + 3] * sWc[(64 + k + 3) * 64 + tid];
            }
#pragma unroll
            for (int k = 0; k < 8; k += 4) {
                a0 += rdb[k] * sWd[k * 64 + tid];
                a1 += rdb[k + 1] * sWd[(k + 1) * 64 + tid];
                a2 += rdb[k + 2] * sWd[(k + 2) * 64 + tid];
                a3 += rdb[k + 3] * sWd[(k + 3) * 64 + tid];
            }
            sx[tid] = fmaxf((a0 + a1) + (a2 + a3), 0.f);
        }
        __syncthreads();
        {
            float g0 = lb[tid], g1 = 0.f, g2 = 0.f, g3 = 0.f;
#pragma unroll 8
            for (int k = 0; k < 64; k += 4) {
                g0 += sx[k] * Wi[k * 512 + tid];
                g1 += sx[k + 1] * Wi[(k + 1) * 512 + tid];
                g2 += sx[k + 2] * Wi[(k + 2) * 512 + tid];
                g3 += sx[k + 3] * Wi[(k + 3) * 512 + tid];
            }
#pragma unroll 8
            for (int k = 0; k < 128; k += 4) {
                g0 += sh[k] * Wh[k * 512 + tid];
                g1 += sh[k + 1] * Wh[(k + 1) * 512 + tid];
                g2 += sh[k + 2] * Wh[(k + 2) * 512 + tid];
                g3 += sh[k + 3] * Wh[(k + 3) * 512 + tid];
            }
            sgate[tid] = (g0 + g1) + (g2 + g3);
        }
        __syncthreads();
        if (tid < 128) {
            float ig = sgate[tid], fg = sgate[128 + tid];
            float gg = sgate[256 + tid], og = sgate[384 + tid];
            float c = sigmf(fg) * scc[tid] + sigmf(ig) * tanhf(gg);
            float hv = sigmf(og) * tanhf(c);
            scc[tid] = c;
            sh[tid] = hv;
        }
        __syncthreads();
        if (tid < 12) {
            float z = shb[tid];
#pragma unroll 8
            for (int k = 0; k < 128; k++) z += sh[k] * shW[k * 12 + tid];
            zsh[tid] = z;
        }
        __syncthreads();
        if (tid < 12) {
            float z = zsh[tid];
            float outv;
            int g = tid / 3;
            if (g == 0) outv = z;
            else if (g == 1) outv = ((z > 20.f) ? z : log1pf(expf(z))) + 1e-3f;
            else if (g == 2) outv = sigmf(z);
            else {
                float z0 = zsh[9], z1 = zsh[10], z2 = zsh[11];
                float mm = fmaxf(z0, fmaxf(z1, z2));
                float s = expf(z0 - mm) + expf(z1 - mm) + expf(z2 - mm);
                outv = expf(z - mm) / s;
            }
            outp[((size_t)b * TT + t) * 12 + tid] = outv;
        }
        __syncthreads();
    }
    if (tid < 128) {
        outp[BBATCH * TT * 12 + b * 128 + tid]                = sh[tid];
        outp[BBATCH * TT * 12 + BBATCH * 128 + b * 128 + tid] = scc[tid];
    }
}

// ---------------- launch -----------------------------------------------------
extern "C" void kernel_launch(void* const* d_in, const int* in_sizes, int n_in,
                              void* d_out, int out_size) {
    const float* era5  = (const float*)d_in[0];
    const float* bc    = (const float*)d_in[1];
    const float* bd    = (const float*)d_in[2];
    const float* rc    = (const float*)d_in[3];
    const float* rd    = (const float*)d_in[4];
    const float* Wc_b  = (const float*)d_in[5];
    const float* Wd_b  = (const float*)d_in[6];
    const float* b_b   = (const float*)d_in[7];
    const float* W1    = (const float*)d_in[8];
    const float* asrc1 = (const float*)d_in[9];
    const float* adst1 = (const float*)d_in[10];
    const float* b1    = (const float*)d_in[11];
    const float* W2    = (const float*)d_in[12];
    const float* asrc2 = (const float*)d_in[13];
    const float* adst2 = (const float*)d_in[14];
    const float* b2    = (const float*)d_in[15];
    const float* Wc_r  = (const float*)d_in[16];
    const float* Wd_r  = (const float*)d_in[17];
    const float* b_r   = (const float*)d_in[18];
    const float* Wi    = (const float*)d_in[19];
    const float* Wh    = (const float*)d_in[20];
    const float* lb    = (const float*)d_in[21];
    const float* hW    = (const float*)d_in[22];
    const float* hb    = (const float*)d_in[23];
    const int*   ei    = (const int*)d_in[24];
    const int*   nodes = (const int*)d_in[25];
    float* outp = (float*)d_out;

    float *p_x, *p_h, *p_y, *p_as, *p_ad;
    cudaGetSymbolAddress((void**)&p_x,  g_x);
    cudaGetSymbolAddress((void**)&p_h,  g_h);
    cudaGetSymbolAddress((void**)&p_y,  g_y);
    cudaGetSymbolAddress((void**)&p_as, g_as);
    cudaGetSymbolAddress((void**)&p_ad, g_ad);

    k_cnt_init<<<NN / 256, 256>>>();
    k_hist<<<EE / 256, 256>>>(ei);
    k_scan<<<1, 1024>>>();
    k_scatter<<<(EPAD + 255) / 256, 256>>>(ei);

    k_proj<<<ROWS / 32, 512>>>(era5, bc, bd, Wc_b, Wd_b, b_b);

    k_gemm<<<ROWS / 64, 128>>>(p_x, W1, asrc1, adst1, p_h, p_as, p_ad);
    k_attn<<<ROWS / 4, 128>>>(p_h, p_as, p_ad, b1, p_y, 1);

    k_gemm<<<ROWS / 64, 128>>>(p_y, W2, asrc2, adst2, p_h, p_as, p_ad);
    k_attn<<<ROWS / 4, 128>>>(p_h, p_as, p_ad, b2, p_x, 0);

    k_lstm<<<BBATCH, 512>>>(rc, rd, Wc_r, Wd_r, b_r, Wi, Wh, lb, hW, hb, nodes, outp);
}